// round 3
// baseline (speedup 1.0000x reference)
#include <cuda_runtime.h>
#include <cstdint>

// Problem constants (fixed by the reference)
#define NUM_B     16
#define NUM_N     2048
#define NUM_Q     (NUM_B * NUM_N)     // 32768 queries
#define M_ANCH    8192
#define NPAIRS    (M_ANCH / 2)        // 4096 anchor pairs
#define BLOCK     128
#define QPB       32                  // queries per block (4 threads each)
#define SPLITW    4                   // anchor-dim split
#define CHUNK_PAIRS 512               // pairs per smem chunk
#define NCHUNK    (NPAIRS / CHUNK_PAIRS) // 8

// ---------- packed f32x2 helpers (sm_103a) ----------
__device__ __forceinline__ unsigned long long f2pk(float lo, float hi) {
    unsigned long long r;
    asm("mov.b64 %0, {%1, %2};" : "=l"(r) : "f"(lo), "f"(hi));
    return r;
}
__device__ __forceinline__ void f2upk(unsigned long long v, float& lo, float& hi) {
    asm("mov.b64 {%0, %1}, %2;" : "=f"(lo), "=f"(hi) : "l"(v));
}
__device__ __forceinline__ unsigned long long ffma2(unsigned long long a,
                                                    unsigned long long b,
                                                    unsigned long long c) {
    unsigned long long d;
    asm("fma.rn.f32x2 %0, %1, %2, %3;" : "=l"(d) : "l"(a), "l"(b), "l"(c));
    return d;
}

// SoA smem: 4 arrays of packed dim-pairs (16B rows, consecutive => conflict-free
// for the 4 split-lanes reading rows 4j+0..3) + packed norm array.
__global__ __launch_bounds__(BLOCK, 6)
void cold_diffusion_nn_kernel(const float* __restrict__ x_start,
                              const float* __restrict__ anchors,
                              const float* __restrict__ sqrt_ac,
                              const float* __restrict__ sqrt_om_ac,
                              const int*   __restrict__ t,
                              float*       __restrict__ out) {
    __shared__ __align__(16) ulonglong2 s01[CHUNK_PAIRS];
    __shared__ __align__(16) ulonglong2 s23[CHUNK_PAIRS];
    __shared__ __align__(16) ulonglong2 s45[CHUNK_PAIRS];
    __shared__ __align__(16) ulonglong2 s67[CHUNK_PAIRS];
    __shared__ __align__(16) unsigned long long snrm[CHUNK_PAIRS];

    const int tid   = threadIdx.x;
    const int split = tid & 3;                    // which quarter of anchors
    const int q     = blockIdx.x * QPB + (tid >> 2);

    // Load this thread's query vector (8 floats = 2x float4)
    const float4* x4 = reinterpret_cast<const float4*>(x_start);
    float4 xv0 = x4[2 * q];
    float4 xv1 = x4[2 * q + 1];

    // Duplicate-pack query dims
    unsigned long long xx0 = f2pk(xv0.x, xv0.x);
    unsigned long long xx1 = f2pk(xv0.y, xv0.y);
    unsigned long long xx2 = f2pk(xv0.z, xv0.z);
    unsigned long long xx3 = f2pk(xv0.w, xv0.w);
    unsigned long long xx4 = f2pk(xv1.x, xv1.x);
    unsigned long long xx5 = f2pk(xv1.y, xv1.y);
    unsigned long long xx6 = f2pk(xv1.z, xv1.z);
    unsigned long long xx7 = f2pk(xv1.w, xv1.w);

    float best = -3.402823466e38f;  // maximize y = x.a - 0.5*||a||^2
    int   bi   = 0;

    const float4* a4 = reinterpret_cast<const float4*>(anchors);

    for (int c = 0; c < NCHUNK; c++) {
        const int pair_base = c * CHUNK_PAIRS;
        __syncthreads();
        // Cooperative SoA fill
        for (int j = tid; j < CHUNK_PAIRS; j += BLOCK) {
            const int a0 = (pair_base + j) * 2;
            float4 p0 = a4[a0 * 2];
            float4 p1 = a4[a0 * 2 + 1];
            float4 q0 = a4[a0 * 2 + 2];
            float4 q1 = a4[a0 * 2 + 3];
            float n0 = p0.x * p0.x + p0.y * p0.y + p0.z * p0.z + p0.w * p0.w
                     + p1.x * p1.x + p1.y * p1.y + p1.z * p1.z + p1.w * p1.w;
            float n1 = q0.x * q0.x + q0.y * q0.y + q0.z * q0.z + q0.w * q0.w
                     + q1.x * q1.x + q1.y * q1.y + q1.z * q1.z + q1.w * q1.w;
            s01[j] = make_ulonglong2(f2pk(p0.x, q0.x), f2pk(p0.y, q0.y));
            s23[j] = make_ulonglong2(f2pk(p0.z, q0.z), f2pk(p0.w, q0.w));
            s45[j] = make_ulonglong2(f2pk(p1.x, q1.x), f2pk(p1.y, q1.y));
            s67[j] = make_ulonglong2(f2pk(p1.z, q1.z), f2pk(p1.w, q1.w));
            snrm[j] = f2pk(-0.5f * n0, -0.5f * n1);
        }
        __syncthreads();

        // Scan this thread's quarter: rows 4*jj + split, unrolled by 2.
        #pragma unroll 2
        for (int jj = 0; jj < CHUNK_PAIRS / SPLITW; jj += 2) {
            const int ja = jj * 4 + split;
            const int jb = ja + 4;

            ulonglong2 a01 = s01[ja], b01 = s01[jb];
            ulonglong2 a23 = s23[ja], b23 = s23[jb];
            ulonglong2 a45 = s45[ja], b45 = s45[jb];
            ulonglong2 a67 = s67[ja], b67 = s67[jb];
            unsigned long long na = snrm[ja];
            unsigned long long nb = snrm[jb];

            unsigned long long accA = na;
            unsigned long long accB = nb;
            accA = ffma2(xx0, a01.x, accA);  accB = ffma2(xx0, b01.x, accB);
            accA = ffma2(xx1, a01.y, accA);  accB = ffma2(xx1, b01.y, accB);
            accA = ffma2(xx2, a23.x, accA);  accB = ffma2(xx2, b23.x, accB);
            accA = ffma2(xx3, a23.y, accA);  accB = ffma2(xx3, b23.y, accB);
            accA = ffma2(xx4, a45.x, accA);  accB = ffma2(xx4, b45.x, accB);
            accA = ffma2(xx5, a45.y, accA);  accB = ffma2(xx5, b45.y, accB);
            accA = ffma2(xx6, a67.x, accA);  accB = ffma2(xx6, b67.x, accB);
            accA = ffma2(xx7, a67.y, accA);  accB = ffma2(xx7, b67.y, accB);

            float s0, s1, s2, s3;
            f2upk(accA, s0, s1);
            f2upk(accB, s2, s3);
            const int ia = (pair_base + ja) * 2;
            const int ib = (pair_base + jb) * 2;
            // strict '>' keeps earliest index on ties (argmin-first semantics)
            if (s0 > best) { best = s0; bi = ia; }
            if (s1 > best) { best = s1; bi = ia + 1; }
            if (s2 > best) { best = s2; bi = ib; }
            if (s3 > best) { best = s3; bi = ib + 1; }
        }
    }

    // Reduce the 4 split-lanes of each query (lanes (l&~3)+0..3, same warp).
    #pragma unroll
    for (int off = 1; off <= 2; off <<= 1) {
        float ob = __shfl_xor_sync(0xFFFFFFFFu, best, off);
        int   oi = __shfl_xor_sync(0xFFFFFFFFu, bi,   off);
        if (ob > best || (ob == best && oi < bi)) { best = ob; bi = oi; }
    }

    if (split == 0) {
        // Epilogue: out = sa*x + sb*anchors[bi]
        const int b  = q >> 11;           // q / 2048
        const int tt = t[b];
        const float sa = sqrt_ac[tt];
        const float sb = sqrt_om_ac[tt];

        float4 m0 = a4[2 * bi];
        float4 m1 = a4[2 * bi + 1];
        float4 o0, o1;
        o0.x = sa * xv0.x + sb * m0.x;
        o0.y = sa * xv0.y + sb * m0.y;
        o0.z = sa * xv0.z + sb * m0.z;
        o0.w = sa * xv0.w + sb * m0.w;
        o1.x = sa * xv1.x + sb * m1.x;
        o1.y = sa * xv1.y + sb * m1.y;
        o1.z = sa * xv1.z + sb * m1.z;
        o1.w = sa * xv1.w + sb * m1.w;

        float4* out4 = reinterpret_cast<float4*>(out);
        out4[2 * q]     = o0;
        out4[2 * q + 1] = o1;
    }
}

extern "C" void kernel_launch(void* const* d_in, const int* in_sizes, int n_in,
                              void* d_out, int out_size) {
    const float* x_start   = (const float*)d_in[0];   // [16,2048,4,2]
    const float* anchors   = (const float*)d_in[1];   // [8192,4,2]
    const float* sqrt_ac   = (const float*)d_in[2];   // [1000]
    const float* sqrt_omac = (const float*)d_in[3];   // [1000]
    const int*   t         = (const int*)d_in[4];     // [16]
    float*       out       = (float*)d_out;           // [16,2048,4,2]

    (void)in_sizes; (void)n_in; (void)out_size;

    cold_diffusion_nn_kernel<<<NUM_Q / QPB, BLOCK>>>(
        x_start, anchors, sqrt_ac, sqrt_omac, t, out);
}

// round 4
// speedup vs baseline: 2.3246x; 2.3246x over previous
#include <cuda_runtime.h>
#include <cstdint>

// Problem constants (fixed by the reference)
#define NUM_B     16
#define NUM_N     2048
#define NUM_Q     (NUM_B * NUM_N)     // 32768 queries
#define M_ANCH    8192
#define NPAIRS    (M_ANCH / 2)        // 4096 anchor pairs
#define BLOCK     128
#define QPT       4                   // queries per thread (register tile)
#define QPB       (BLOCK * QPT)       // 512 queries per CTA
#define S_SPLIT   8                   // anchor splits (blockIdx.y)
#define PAIRS_PER_SPLIT (NPAIRS / S_SPLIT) // 512 pairs = 1024 anchors

// Partial results: [split][query]
__device__ float g_part_best[S_SPLIT * NUM_Q];
__device__ int   g_part_idx [S_SPLIT * NUM_Q];

// ---------- packed f32x2 helpers (sm_103a) ----------
__device__ __forceinline__ unsigned long long f2pk(float lo, float hi) {
    unsigned long long r;
    asm("mov.b64 %0, {%1, %2};" : "=l"(r) : "f"(lo), "f"(hi));
    return r;
}
__device__ __forceinline__ void f2upk(unsigned long long v, float& lo, float& hi) {
    asm("mov.b64 {%0, %1}, %2;" : "=f"(lo), "=f"(hi) : "l"(v));
}
__device__ __forceinline__ unsigned long long ffma2(unsigned long long a,
                                                    unsigned long long b,
                                                    unsigned long long c) {
    unsigned long long d;
    asm("fma.rn.f32x2 %0, %1, %2, %3;" : "=l"(d) : "l"(a), "l"(b), "l"(c));
    return d;
}

// Main kernel: each CTA = 512 queries x 512 anchor-pairs (one smem chunk, loaded once).
// Each thread: 4 queries vs the broadcast pair stream.
__global__ __launch_bounds__(BLOCK, 4)
void nn_partial_kernel(const float* __restrict__ x_start,
                       const float* __restrict__ anchors) {
    __shared__ __align__(16) ulonglong2 s01[PAIRS_PER_SPLIT];
    __shared__ __align__(16) ulonglong2 s23[PAIRS_PER_SPLIT];
    __shared__ __align__(16) ulonglong2 s45[PAIRS_PER_SPLIT];
    __shared__ __align__(16) ulonglong2 s67[PAIRS_PER_SPLIT];
    __shared__ __align__(16) unsigned long long snrm[PAIRS_PER_SPLIT];

    const int tid   = threadIdx.x;
    const int split = blockIdx.y;
    const int q0    = blockIdx.x * QPB + tid * QPT;   // 4 consecutive queries
    const int pair_base = split * PAIRS_PER_SPLIT;

    const float4* a4 = reinterpret_cast<const float4*>(anchors);
    const float4* x4 = reinterpret_cast<const float4*>(x_start);

    // Cooperative smem fill (pair-packed SoA, broadcast-friendly rows)
    for (int j = tid; j < PAIRS_PER_SPLIT; j += BLOCK) {
        const int a0 = (pair_base + j) * 2;
        float4 p0 = a4[a0 * 2];
        float4 p1 = a4[a0 * 2 + 1];
        float4 r0 = a4[a0 * 2 + 2];
        float4 r1 = a4[a0 * 2 + 3];
        float n0 = p0.x * p0.x + p0.y * p0.y + p0.z * p0.z + p0.w * p0.w
                 + p1.x * p1.x + p1.y * p1.y + p1.z * p1.z + p1.w * p1.w;
        float n1 = r0.x * r0.x + r0.y * r0.y + r0.z * r0.z + r0.w * r0.w
                 + r1.x * r1.x + r1.y * r1.y + r1.z * r1.z + r1.w * r1.w;
        s01[j] = make_ulonglong2(f2pk(p0.x, r0.x), f2pk(p0.y, r0.y));
        s23[j] = make_ulonglong2(f2pk(p0.z, r0.z), f2pk(p0.w, r0.w));
        s45[j] = make_ulonglong2(f2pk(p1.x, r1.x), f2pk(p1.y, r1.y));
        s67[j] = make_ulonglong2(f2pk(p1.z, r1.z), f2pk(p1.w, r1.w));
        snrm[j] = f2pk(-0.5f * n0, -0.5f * n1);
    }

    // Load 4 queries, duplicate-packed: xx[k][d] = {x_k[d], x_k[d]}
    unsigned long long xx[QPT][8];
    #pragma unroll
    for (int k = 0; k < QPT; k++) {
        float4 v0 = x4[2 * (q0 + k)];
        float4 v1 = x4[2 * (q0 + k) + 1];
        xx[k][0] = f2pk(v0.x, v0.x);
        xx[k][1] = f2pk(v0.y, v0.y);
        xx[k][2] = f2pk(v0.z, v0.z);
        xx[k][3] = f2pk(v0.w, v0.w);
        xx[k][4] = f2pk(v1.x, v1.x);
        xx[k][5] = f2pk(v1.y, v1.y);
        xx[k][6] = f2pk(v1.z, v1.z);
        xx[k][7] = f2pk(v1.w, v1.w);
    }

    float best[QPT];
    int   bi[QPT];
    #pragma unroll
    for (int k = 0; k < QPT; k++) { best[k] = -3.402823466e38f; bi[k] = 0; }

    __syncthreads();

    #pragma unroll 1
    for (int j = 0; j < PAIRS_PER_SPLIT; j++) {
        ulonglong2 a01 = s01[j];
        ulonglong2 a23 = s23[j];
        ulonglong2 a45 = s45[j];
        ulonglong2 a67 = s67[j];
        unsigned long long nr = snrm[j];

        unsigned long long acc[QPT];
        #pragma unroll
        for (int k = 0; k < QPT; k++) acc[k] = nr;
        #pragma unroll
        for (int k = 0; k < QPT; k++) acc[k] = ffma2(xx[k][0], a01.x, acc[k]);
        #pragma unroll
        for (int k = 0; k < QPT; k++) acc[k] = ffma2(xx[k][1], a01.y, acc[k]);
        #pragma unroll
        for (int k = 0; k < QPT; k++) acc[k] = ffma2(xx[k][2], a23.x, acc[k]);
        #pragma unroll
        for (int k = 0; k < QPT; k++) acc[k] = ffma2(xx[k][3], a23.y, acc[k]);
        #pragma unroll
        for (int k = 0; k < QPT; k++) acc[k] = ffma2(xx[k][4], a45.x, acc[k]);
        #pragma unroll
        for (int k = 0; k < QPT; k++) acc[k] = ffma2(xx[k][5], a45.y, acc[k]);
        #pragma unroll
        for (int k = 0; k < QPT; k++) acc[k] = ffma2(xx[k][6], a67.x, acc[k]);
        #pragma unroll
        for (int k = 0; k < QPT; k++) acc[k] = ffma2(xx[k][7], a67.y, acc[k]);

        const int ia = (pair_base + j) * 2;
        #pragma unroll
        for (int k = 0; k < QPT; k++) {
            float sc0, sc1;
            f2upk(acc[k], sc0, sc1);
            // strict '>' keeps the earliest index on ties
            if (sc0 > best[k]) { best[k] = sc0; bi[k] = ia; }
            if (sc1 > best[k]) { best[k] = sc1; bi[k] = ia + 1; }
        }
    }

    #pragma unroll
    for (int k = 0; k < QPT; k++) {
        g_part_best[split * NUM_Q + q0 + k] = best[k];
        g_part_idx [split * NUM_Q + q0 + k] = bi[k];
    }
}

// Reduce over the 8 splits + blend epilogue.
__global__ __launch_bounds__(256)
void reduce_blend_kernel(const float* __restrict__ x_start,
                         const float* __restrict__ anchors,
                         const float* __restrict__ sqrt_ac,
                         const float* __restrict__ sqrt_om_ac,
                         const int*   __restrict__ t,
                         float*       __restrict__ out) {
    const int q = blockIdx.x * 256 + threadIdx.x;

    float best = -3.402823466e38f;
    int   bi   = 0;
    // Ascending split order + strict '>' keeps earliest (smallest) index on ties.
    #pragma unroll
    for (int s = 0; s < S_SPLIT; s++) {
        float sc = g_part_best[s * NUM_Q + q];
        int   id = g_part_idx [s * NUM_Q + q];
        if (sc > best) { best = sc; bi = id; }
    }

    const int b  = q >> 11;           // q / 2048
    const int tt = t[b];
    const float sa = sqrt_ac[tt];
    const float sb = sqrt_om_ac[tt];

    const float4* x4 = reinterpret_cast<const float4*>(x_start);
    const float4* a4 = reinterpret_cast<const float4*>(anchors);
    float4 xv0 = x4[2 * q];
    float4 xv1 = x4[2 * q + 1];
    float4 m0  = a4[2 * bi];
    float4 m1  = a4[2 * bi + 1];

    float4 o0, o1;
    o0.x = sa * xv0.x + sb * m0.x;
    o0.y = sa * xv0.y + sb * m0.y;
    o0.z = sa * xv0.z + sb * m0.z;
    o0.w = sa * xv0.w + sb * m0.w;
    o1.x = sa * xv1.x + sb * m1.x;
    o1.y = sa * xv1.y + sb * m1.y;
    o1.z = sa * xv1.z + sb * m1.z;
    o1.w = sa * xv1.w + sb * m1.w;

    float4* out4 = reinterpret_cast<float4*>(out);
    out4[2 * q]     = o0;
    out4[2 * q + 1] = o1;
}

extern "C" void kernel_launch(void* const* d_in, const int* in_sizes, int n_in,
                              void* d_out, int out_size) {
    const float* x_start   = (const float*)d_in[0];   // [16,2048,4,2]
    const float* anchors   = (const float*)d_in[1];   // [8192,4,2]
    const float* sqrt_ac   = (const float*)d_in[2];   // [1000]
    const float* sqrt_omac = (const float*)d_in[3];   // [1000]
    const int*   t         = (const int*)d_in[4];     // [16]
    float*       out       = (float*)d_out;           // [16,2048,4,2]

    (void)in_sizes; (void)n_in; (void)out_size;

    dim3 grid1(NUM_Q / QPB, S_SPLIT);   // 64 x 8 = 512 CTAs
    nn_partial_kernel<<<grid1, BLOCK>>>(x_start, anchors);
    reduce_blend_kernel<<<NUM_Q / 256, 256>>>(x_start, anchors, sqrt_ac,
                                              sqrt_omac, t, out);
}

// round 5
// speedup vs baseline: 2.7078x; 1.1649x over previous
#include <cuda_runtime.h>
#include <cstdint>

// Problem constants (fixed by the reference)
#define NUM_B     16
#define NUM_N     2048
#define NUM_Q     (NUM_B * NUM_N)     // 32768 queries
#define M_ANCH    8192
#define NPAIRS    (M_ANCH / 2)        // 4096 anchor pairs
#define BLOCK     128
#define QPT       4                   // queries per thread (register tile)
#define QPB       (BLOCK * QPT)       // 512 queries per CTA
#define S_SPLIT   16                  // anchor splits (blockIdx.y)
#define PAIRS_PER_SPLIT (NPAIRS / S_SPLIT) // 256 pairs = 512 anchors

// Partial results: [split][query]
__device__ float g_part_best[S_SPLIT * NUM_Q];
__device__ int   g_part_idx [S_SPLIT * NUM_Q];

// ---------- packed f32x2 helpers (sm_103a) ----------
__device__ __forceinline__ unsigned long long f2pk(float lo, float hi) {
    unsigned long long r;
    asm("mov.b64 %0, {%1, %2};" : "=l"(r) : "f"(lo), "f"(hi));
    return r;
}
__device__ __forceinline__ void f2upk(unsigned long long v, float& lo, float& hi) {
    asm("mov.b64 {%0, %1}, %2;" : "=f"(lo), "=f"(hi) : "l"(v));
}
__device__ __forceinline__ unsigned long long ffma2(unsigned long long a,
                                                    unsigned long long b,
                                                    unsigned long long c) {
    unsigned long long d;
    asm("fma.rn.f32x2 %0, %1, %2, %3;" : "=l"(d) : "l"(a), "l"(b), "l"(c));
    return d;
}

// Main kernel: CTA = 512 queries x 256 anchor-pairs (one smem chunk, loaded once).
// Each thread: 4 queries vs the broadcast pair stream.
__global__ __launch_bounds__(BLOCK, 4)
void nn_partial_kernel(const float* __restrict__ x_start,
                       const float* __restrict__ anchors) {
    __shared__ __align__(16) ulonglong2 s01[PAIRS_PER_SPLIT];
    __shared__ __align__(16) ulonglong2 s23[PAIRS_PER_SPLIT];
    __shared__ __align__(16) ulonglong2 s45[PAIRS_PER_SPLIT];
    __shared__ __align__(16) ulonglong2 s67[PAIRS_PER_SPLIT];
    __shared__ __align__(16) unsigned long long snrm[PAIRS_PER_SPLIT];

    const int tid   = threadIdx.x;
    const int split = blockIdx.y;
    const int q0    = blockIdx.x * QPB + tid * QPT;   // 4 consecutive queries
    const int pair_base = split * PAIRS_PER_SPLIT;

    const float4* a4 = reinterpret_cast<const float4*>(anchors);
    const float4* x4 = reinterpret_cast<const float4*>(x_start);

    // Cooperative smem fill (pair-packed SoA, broadcast-friendly rows)
    for (int j = tid; j < PAIRS_PER_SPLIT; j += BLOCK) {
        const int a0 = (pair_base + j) * 2;
        float4 p0 = a4[a0 * 2];
        float4 p1 = a4[a0 * 2 + 1];
        float4 r0 = a4[a0 * 2 + 2];
        float4 r1 = a4[a0 * 2 + 3];
        float n0 = p0.x * p0.x + p0.y * p0.y + p0.z * p0.z + p0.w * p0.w
                 + p1.x * p1.x + p1.y * p1.y + p1.z * p1.z + p1.w * p1.w;
        float n1 = r0.x * r0.x + r0.y * r0.y + r0.z * r0.z + r0.w * r0.w
                 + r1.x * r1.x + r1.y * r1.y + r1.z * r1.z + r1.w * r1.w;
        s01[j] = make_ulonglong2(f2pk(p0.x, r0.x), f2pk(p0.y, r0.y));
        s23[j] = make_ulonglong2(f2pk(p0.z, r0.z), f2pk(p0.w, r0.w));
        s45[j] = make_ulonglong2(f2pk(p1.x, r1.x), f2pk(p1.y, r1.y));
        s67[j] = make_ulonglong2(f2pk(p1.z, r1.z), f2pk(p1.w, r1.w));
        snrm[j] = f2pk(-0.5f * n0, -0.5f * n1);
    }

    // Load 4 queries, duplicate-packed: xx[k][d] = {x_k[d], x_k[d]}
    unsigned long long xx[QPT][8];
    #pragma unroll
    for (int k = 0; k < QPT; k++) {
        float4 v0 = x4[2 * (q0 + k)];
        float4 v1 = x4[2 * (q0 + k) + 1];
        xx[k][0] = f2pk(v0.x, v0.x);
        xx[k][1] = f2pk(v0.y, v0.y);
        xx[k][2] = f2pk(v0.z, v0.z);
        xx[k][3] = f2pk(v0.w, v0.w);
        xx[k][4] = f2pk(v1.x, v1.x);
        xx[k][5] = f2pk(v1.y, v1.y);
        xx[k][6] = f2pk(v1.z, v1.z);
        xx[k][7] = f2pk(v1.w, v1.w);
    }

    float best[QPT];
    int   bi[QPT];
    #pragma unroll
    for (int k = 0; k < QPT; k++) { best[k] = -3.402823466e38f; bi[k] = 0; }

    __syncthreads();

    #pragma unroll 2
    for (int j = 0; j < PAIRS_PER_SPLIT; j++) {
        ulonglong2 a01 = s01[j];
        ulonglong2 a23 = s23[j];
        ulonglong2 a45 = s45[j];
        ulonglong2 a67 = s67[j];
        unsigned long long nr = snrm[j];

        unsigned long long acc[QPT];
        #pragma unroll
        for (int k = 0; k < QPT; k++) acc[k] = nr;
        #pragma unroll
        for (int k = 0; k < QPT; k++) acc[k] = ffma2(xx[k][0], a01.x, acc[k]);
        #pragma unroll
        for (int k = 0; k < QPT; k++) acc[k] = ffma2(xx[k][1], a01.y, acc[k]);
        #pragma unroll
        for (int k = 0; k < QPT; k++) acc[k] = ffma2(xx[k][2], a23.x, acc[k]);
        #pragma unroll
        for (int k = 0; k < QPT; k++) acc[k] = ffma2(xx[k][3], a23.y, acc[k]);
        #pragma unroll
        for (int k = 0; k < QPT; k++) acc[k] = ffma2(xx[k][4], a45.x, acc[k]);
        #pragma unroll
        for (int k = 0; k < QPT; k++) acc[k] = ffma2(xx[k][5], a45.y, acc[k]);
        #pragma unroll
        for (int k = 0; k < QPT; k++) acc[k] = ffma2(xx[k][6], a67.x, acc[k]);
        #pragma unroll
        for (int k = 0; k < QPT; k++) acc[k] = ffma2(xx[k][7], a67.y, acc[k]);

        const int ia = (pair_base + j) * 2;
        #pragma unroll
        for (int k = 0; k < QPT; k++) {
            float sc0, sc1;
            f2upk(acc[k], sc0, sc1);
            // Pair-max first, then single predicated update.
            // Ties: sc1==sc0 -> lower index; m==best -> keep earlier index.
            float m  = fmaxf(sc0, sc1);
            int   ii = ia + (sc1 > sc0 ? 1 : 0);
            bool  up = m > best[k];
            best[k] = up ? m  : best[k];
            bi[k]   = up ? ii : bi[k];
        }
    }

    #pragma unroll
    for (int k = 0; k < QPT; k++) {
        g_part_best[split * NUM_Q + q0 + k] = best[k];
        g_part_idx [split * NUM_Q + q0 + k] = bi[k];
    }
}

// Reduce over the 16 splits + blend epilogue.
__global__ __launch_bounds__(256)
void reduce_blend_kernel(const float* __restrict__ x_start,
                         const float* __restrict__ anchors,
                         const float* __restrict__ sqrt_ac,
                         const float* __restrict__ sqrt_om_ac,
                         const int*   __restrict__ t,
                         float*       __restrict__ out) {
    const int q = blockIdx.x * 256 + threadIdx.x;

    float best = -3.402823466e38f;
    int   bi   = 0;
    // Ascending split order + strict '>' keeps earliest (smallest) index on ties.
    #pragma unroll
    for (int s = 0; s < S_SPLIT; s++) {
        float sc = g_part_best[s * NUM_Q + q];
        int   id = g_part_idx [s * NUM_Q + q];
        if (sc > best) { best = sc; bi = id; }
    }

    const int b  = q >> 11;           // q / 2048
    const int tt = t[b];
    const float sa = sqrt_ac[tt];
    const float sb = sqrt_om_ac[tt];

    const float4* x4 = reinterpret_cast<const float4*>(x_start);
    const float4* a4 = reinterpret_cast<const float4*>(anchors);
    float4 xv0 = x4[2 * q];
    float4 xv1 = x4[2 * q + 1];
    float4 m0  = a4[2 * bi];
    float4 m1  = a4[2 * bi + 1];

    float4 o0, o1;
    o0.x = sa * xv0.x + sb * m0.x;
    o0.y = sa * xv0.y + sb * m0.y;
    o0.z = sa * xv0.z + sb * m0.z;
    o0.w = sa * xv0.w + sb * m0.w;
    o1.x = sa * xv1.x + sb * m1.x;
    o1.y = sa * xv1.y + sb * m1.y;
    o1.z = sa * xv1.z + sb * m1.z;
    o1.w = sa * xv1.w + sb * m1.w;

    float4* out4 = reinterpret_cast<float4*>(out);
    out4[2 * q]     = o0;
    out4[2 * q + 1] = o1;
}

extern "C" void kernel_launch(void* const* d_in, const int* in_sizes, int n_in,
                              void* d_out, int out_size) {
    const float* x_start   = (const float*)d_in[0];   // [16,2048,4,2]
    const float* anchors   = (const float*)d_in[1];   // [8192,4,2]
    const float* sqrt_ac   = (const float*)d_in[2];   // [1000]
    const float* sqrt_omac = (const float*)d_in[3];   // [1000]
    const int*   t         = (const int*)d_in[4];     // [16]
    float*       out       = (float*)d_out;           // [16,2048,4,2]

    (void)in_sizes; (void)n_in; (void)out_size;

    dim3 grid1(NUM_Q / QPB, S_SPLIT);   // 64 x 16 = 1024 CTAs
    nn_partial_kernel<<<grid1, BLOCK>>>(x_start, anchors);
    reduce_blend_kernel<<<NUM_Q / 256, 256>>>(x_start, anchors, sqrt_ac,
                                              sqrt_omac, t, out);
}

// round 7
// speedup vs baseline: 2.8829x; 1.0646x over previous
#include <cuda_runtime.h>
#include <cstdint>

// Problem constants (fixed by the reference)
#define NUM_B     16
#define NUM_N     2048
#define NUM_Q     (NUM_B * NUM_N)     // 32768 queries
#define M_ANCH    8192
#define NPAIRS    (M_ANCH / 2)        // 4096 anchor pairs
#define BLOCK     128
#define QPT       4                   // queries per thread (register tile)
#define QPB       (BLOCK * QPT)       // 512 queries per CTA
#define S_SPLIT   16                  // anchor splits (blockIdx.y)
#define PAIRS_PER_SPLIT (NPAIRS / S_SPLIT) // 256 pairs = 512 anchors

// Packed (score,index) winners. Encoding guarantees 0 < any real entry, so the
// blend kernel re-zeroing after use re-arms the buffer for the next replay.
__device__ unsigned long long g_best[NUM_Q];   // zero-initialized at load

// ---------- packed f32x2 helpers (sm_103a) ----------
__device__ __forceinline__ unsigned long long f2pk(float lo, float hi) {
    unsigned long long r;
    asm("mov.b64 %0, {%1, %2};" : "=l"(r) : "f"(lo), "f"(hi));
    return r;
}
__device__ __forceinline__ void f2upk(unsigned long long v, float& lo, float& hi) {
    asm("mov.b64 {%0, %1}, %2;" : "=f"(lo), "=f"(hi) : "l"(v));
}
__device__ __forceinline__ unsigned long long ffma2(unsigned long long a,
                                                    unsigned long long b,
                                                    unsigned long long c) {
    unsigned long long d;
    asm("fma.rn.f32x2 %0, %1, %2, %3;" : "=l"(d) : "l"(a), "l"(b), "l"(c));
    return d;
}

// Monotonic fp32 -> u32 (order-preserving, all finite values map >= 0x00800000)
__device__ __forceinline__ unsigned int fmono(float f) {
    unsigned int b = __float_as_uint(f);
    return (b & 0x80000000u) ? ~b : (b | 0x80000000u);
}

// Main kernel: CTA = 512 queries x 256 anchor-pairs (one smem chunk).
// Each thread: 4 queries vs broadcast pair stream; ends with one atomicMax/query.
__global__ __launch_bounds__(BLOCK, 4)
void nn_partial_kernel(const float* __restrict__ x_start,
                       const float* __restrict__ anchors) {
    __shared__ __align__(16) ulonglong2 s01[PAIRS_PER_SPLIT];
    __shared__ __align__(16) ulonglong2 s23[PAIRS_PER_SPLIT];
    __shared__ __align__(16) ulonglong2 s45[PAIRS_PER_SPLIT];
    __shared__ __align__(16) ulonglong2 s67[PAIRS_PER_SPLIT];
    __shared__ __align__(16) unsigned long long snrm[PAIRS_PER_SPLIT];

    const int tid   = threadIdx.x;
    const int split = blockIdx.y;
    const int q0    = blockIdx.x * QPB + tid * QPT;   // 4 consecutive queries
    const int pair_base = split * PAIRS_PER_SPLIT;

    const float4* a4 = reinterpret_cast<const float4*>(anchors);
    const float4* x4 = reinterpret_cast<const float4*>(x_start);

    // Cooperative smem fill (pair-packed SoA, broadcast-friendly rows)
    for (int j = tid; j < PAIRS_PER_SPLIT; j += BLOCK) {
        const int a0 = (pair_base + j) * 2;
        float4 p0 = a4[a0 * 2];
        float4 p1 = a4[a0 * 2 + 1];
        float4 r0 = a4[a0 * 2 + 2];
        float4 r1 = a4[a0 * 2 + 3];
        float n0 = p0.x * p0.x + p0.y * p0.y + p0.z * p0.z + p0.w * p0.w
                 + p1.x * p1.x + p1.y * p1.y + p1.z * p1.z + p1.w * p1.w;
        float n1 = r0.x * r0.x + r0.y * r0.y + r0.z * r0.z + r0.w * r0.w
                 + r1.x * r1.x + r1.y * r1.y + r1.z * r1.z + r1.w * r1.w;
        s01[j] = make_ulonglong2(f2pk(p0.x, r0.x), f2pk(p0.y, r0.y));
        s23[j] = make_ulonglong2(f2pk(p0.z, r0.z), f2pk(p0.w, r0.w));
        s45[j] = make_ulonglong2(f2pk(p1.x, r1.x), f2pk(p1.y, r1.y));
        s67[j] = make_ulonglong2(f2pk(p1.z, r1.z), f2pk(p1.w, r1.w));
        snrm[j] = f2pk(-0.5f * n0, -0.5f * n1);
    }

    // Load 4 queries, duplicate-packed: xx[k][d] = {x_k[d], x_k[d]}
    unsigned long long xx[QPT][8];
    #pragma unroll
    for (int k = 0; k < QPT; k++) {
        float4 v0 = x4[2 * (q0 + k)];
        float4 v1 = x4[2 * (q0 + k) + 1];
        xx[k][0] = f2pk(v0.x, v0.x);
        xx[k][1] = f2pk(v0.y, v0.y);
        xx[k][2] = f2pk(v0.z, v0.z);
        xx[k][3] = f2pk(v0.w, v0.w);
        xx[k][4] = f2pk(v1.x, v1.x);
        xx[k][5] = f2pk(v1.y, v1.y);
        xx[k][6] = f2pk(v1.z, v1.z);
        xx[k][7] = f2pk(v1.w, v1.w);
    }

    float best[QPT];
    int   bi[QPT];
    #pragma unroll
    for (int k = 0; k < QPT; k++) { best[k] = -3.402823466e38f; bi[k] = 0; }

    __syncthreads();

    #pragma unroll 2
    for (int j = 0; j < PAIRS_PER_SPLIT; j++) {
        ulonglong2 a01 = s01[j];
        ulonglong2 a23 = s23[j];
        ulonglong2 a45 = s45[j];
        ulonglong2 a67 = s67[j];
        unsigned long long nr = snrm[j];

        unsigned long long acc[QPT];
        #pragma unroll
        for (int k = 0; k < QPT; k++) acc[k] = nr;
        #pragma unroll
        for (int k = 0; k < QPT; k++) acc[k] = ffma2(xx[k][0], a01.x, acc[k]);
        #pragma unroll
        for (int k = 0; k < QPT; k++) acc[k] = ffma2(xx[k][1], a01.y, acc[k]);
        #pragma unroll
        for (int k = 0; k < QPT; k++) acc[k] = ffma2(xx[k][2], a23.x, acc[k]);
        #pragma unroll
        for (int k = 0; k < QPT; k++) acc[k] = ffma2(xx[k][3], a23.y, acc[k]);
        #pragma unroll
        for (int k = 0; k < QPT; k++) acc[k] = ffma2(xx[k][4], a45.x, acc[k]);
        #pragma unroll
        for (int k = 0; k < QPT; k++) acc[k] = ffma2(xx[k][5], a45.y, acc[k]);
        #pragma unroll
        for (int k = 0; k < QPT; k++) acc[k] = ffma2(xx[k][6], a67.x, acc[k]);
        #pragma unroll
        for (int k = 0; k < QPT; k++) acc[k] = ffma2(xx[k][7], a67.y, acc[k]);

        const int ia = (pair_base + j) * 2;
        #pragma unroll
        for (int k = 0; k < QPT; k++) {
            float sc0, sc1;
            f2upk(acc[k], sc0, sc1);
            // Pair-max first, then single predicated update.
            // Ties: sc1==sc0 -> lower index; m==best -> keep earlier index.
            float m  = fmaxf(sc0, sc1);
            int   ii = ia + (sc1 > sc0 ? 1 : 0);
            bool  up = m > best[k];
            best[k] = up ? m  : best[k];
            bi[k]   = up ? ii : bi[k];
        }
    }

    // Deterministic global combine: max on (mono(score), ~idx) packed u64.
    // Higher score wins; equal score -> larger (0xFFFFFFFF - idx) wins = smaller idx.
    #pragma unroll
    for (int k = 0; k < QPT; k++) {
        unsigned long long pk =
            (((unsigned long long)fmono(best[k])) << 32) |
            (unsigned long long)(0xFFFFFFFFu - (unsigned int)bi[k]);
        atomicMax(&g_best[q0 + k], pk);
    }
}

// Blend epilogue: read packed winner, produce output, re-zero slot for next replay.
__global__ __launch_bounds__(BLOCK)
void blend_kernel(const float* __restrict__ x_start,
                  const float* __restrict__ anchors,
                  const float* __restrict__ sqrt_ac,
                  const float* __restrict__ sqrt_om_ac,
                  const int*   __restrict__ t,
                  float*       __restrict__ out) {
    const int q = blockIdx.x * BLOCK + threadIdx.x;

    unsigned long long pk = g_best[q];
    const int bi = (int)(0xFFFFFFFFu - (unsigned int)pk);
    g_best[q] = 0ull;                 // re-arm for the next graph replay

    const int b  = q >> 11;           // q / 2048
    const int tt = t[b];
    const float sa = sqrt_ac[tt];
    const float sb = sqrt_om_ac[tt];

    const float4* x4 = reinterpret_cast<const float4*>(x_start);
    const float4* a4 = reinterpret_cast<const float4*>(anchors);
    float4 xv0 = x4[2 * q];
    float4 xv1 = x4[2 * q + 1];
    float4 m0  = a4[2 * bi];
    float4 m1  = a4[2 * bi + 1];

    float4 o0, o1;
    o0.x = sa * xv0.x + sb * m0.x;
    o0.y = sa * xv0.y + sb * m0.y;
    o0.z = sa * xv0.z + sb * m0.z;
    o0.w = sa * xv0.w + sb * m0.w;
    o1.x = sa * xv1.x + sb * m1.x;
    o1.y = sa * xv1.y + sb * m1.y;
    o1.z = sa * xv1.z + sb * m1.z;
    o1.w = sa * xv1.w + sb * m1.w;

    float4* out4 = reinterpret_cast<float4*>(out);
    out4[2 * q]     = o0;
    out4[2 * q + 1] = o1;
}

extern "C" void kernel_launch(void* const* d_in, const int* in_sizes, int n_in,
                              void* d_out, int out_size) {
    const float* x_start   = (const float*)d_in[0];   // [16,2048,4,2]
    const float* anchors   = (const float*)d_in[1];   // [8192,4,2]
    const float* sqrt_ac   = (const float*)d_in[2];   // [1000]
    const float* sqrt_omac = (const float*)d_in[3];   // [1000]
    const int*   t         = (const int*)d_in[4];     // [16]
    float*       out       = (float*)d_out;           // [16,2048,4,2]

    (void)in_sizes; (void)n_in; (void)out_size;

    dim3 grid1(NUM_Q / QPB, S_SPLIT);   // 64 x 16 = 1024 CTAs
    nn_partial_kernel<<<grid1, BLOCK>>>(x_start, anchors);
    blend_kernel<<<NUM_Q / BLOCK, BLOCK>>>(x_start, anchors, sqrt_ac,
                                           sqrt_omac, t, out);
}

// round 8
// speedup vs baseline: 2.9286x; 1.0159x over previous
#include <cuda_runtime.h>
#include <cstdint>

// Problem constants (fixed by the reference)
#define NUM_B     16
#define NUM_N     2048
#define NUM_Q     (NUM_B * NUM_N)     // 32768 queries
#define M_ANCH    8192
#define NPAIRS    (M_ANCH / 2)        // 4096 anchor pairs
#define BLOCK     128
#define QPT       4                   // queries per thread (register tile)
#define QPB       (BLOCK * QPT)       // 512 queries per CTA
#define S_SPLIT   16                  // anchor splits (blockIdx.y)
#define PAIRS_PER_SPLIT (NPAIRS / S_SPLIT) // 256 pairs = 512 anchors
#define NQGROUP   (NUM_Q / QPB)       // 64 query groups

// Packed (score,index) winners. Encoding guarantees 0 < any real entry, so the
// blend path re-zeroing after use re-arms the buffer for the next graph replay.
__device__ unsigned long long g_best[NUM_Q];   // zero-initialized at load
__device__ int g_done[NQGROUP];                // split-arrival counters, zero-init

// ---------- packed f32x2 helpers (sm_103a) ----------
__device__ __forceinline__ unsigned long long f2pk(float lo, float hi) {
    unsigned long long r;
    asm("mov.b64 %0, {%1, %2};" : "=l"(r) : "f"(lo), "f"(hi));
    return r;
}
__device__ __forceinline__ void f2upk(unsigned long long v, float& lo, float& hi) {
    asm("mov.b64 {%0, %1}, %2;" : "=f"(lo), "=f"(hi) : "l"(v));
}
__device__ __forceinline__ unsigned long long ffma2(unsigned long long a,
                                                    unsigned long long b,
                                                    unsigned long long c) {
    unsigned long long d;
    asm("fma.rn.f32x2 %0, %1, %2, %3;" : "=l"(d) : "l"(a), "l"(b), "l"(c));
    return d;
}

// Monotonic fp32 -> u32 (order-preserving)
__device__ __forceinline__ unsigned int fmono(float f) {
    unsigned int b = __float_as_uint(f);
    return (b & 0x80000000u) ? ~b : (b | 0x80000000u);
}

// Fused kernel: CTA = 512 queries x 256 anchor-pairs. After the scan, CTAs
// combine via atomicMax; the last-arriving CTA of each query group blends.
__global__ __launch_bounds__(BLOCK, 4)
void nn_fused_kernel(const float* __restrict__ x_start,
                     const float* __restrict__ anchors,
                     const float* __restrict__ sqrt_ac,
                     const float* __restrict__ sqrt_om_ac,
                     const int*   __restrict__ t,
                     float*       __restrict__ out) {
    __shared__ __align__(16) ulonglong2 s01[PAIRS_PER_SPLIT];
    __shared__ __align__(16) ulonglong2 s23[PAIRS_PER_SPLIT];
    __shared__ __align__(16) ulonglong2 s45[PAIRS_PER_SPLIT];
    __shared__ __align__(16) ulonglong2 s67[PAIRS_PER_SPLIT];
    __shared__ __align__(16) unsigned long long snrm[PAIRS_PER_SPLIT];
    __shared__ int s_old;

    const int tid   = threadIdx.x;
    const int split = blockIdx.y;
    const int q0    = blockIdx.x * QPB + tid * QPT;   // 4 consecutive queries
    const int pair_base = split * PAIRS_PER_SPLIT;

    const float4* a4 = reinterpret_cast<const float4*>(anchors);
    const float4* x4 = reinterpret_cast<const float4*>(x_start);

    // Cooperative smem fill (pair-packed SoA, broadcast-friendly rows)
    for (int j = tid; j < PAIRS_PER_SPLIT; j += BLOCK) {
        const int a0 = (pair_base + j) * 2;
        float4 p0 = a4[a0 * 2];
        float4 p1 = a4[a0 * 2 + 1];
        float4 r0 = a4[a0 * 2 + 2];
        float4 r1 = a4[a0 * 2 + 3];
        float n0 = p0.x * p0.x + p0.y * p0.y + p0.z * p0.z + p0.w * p0.w
                 + p1.x * p1.x + p1.y * p1.y + p1.z * p1.z + p1.w * p1.w;
        float n1 = r0.x * r0.x + r0.y * r0.y + r0.z * r0.z + r0.w * r0.w
                 + r1.x * r1.x + r1.y * r1.y + r1.z * r1.z + r1.w * r1.w;
        s01[j] = make_ulonglong2(f2pk(p0.x, r0.x), f2pk(p0.y, r0.y));
        s23[j] = make_ulonglong2(f2pk(p0.z, r0.z), f2pk(p0.w, r0.w));
        s45[j] = make_ulonglong2(f2pk(p1.x, r1.x), f2pk(p1.y, r1.y));
        s67[j] = make_ulonglong2(f2pk(p1.z, r1.z), f2pk(p1.w, r1.w));
        snrm[j] = f2pk(-0.5f * n0, -0.5f * n1);
    }

    // Load 4 queries, duplicate-packed: xx[k][d] = {x_k[d], x_k[d]}
    unsigned long long xx[QPT][8];
    #pragma unroll
    for (int k = 0; k < QPT; k++) {
        float4 v0 = x4[2 * (q0 + k)];
        float4 v1 = x4[2 * (q0 + k) + 1];
        xx[k][0] = f2pk(v0.x, v0.x);
        xx[k][1] = f2pk(v0.y, v0.y);
        xx[k][2] = f2pk(v0.z, v0.z);
        xx[k][3] = f2pk(v0.w, v0.w);
        xx[k][4] = f2pk(v1.x, v1.x);
        xx[k][5] = f2pk(v1.y, v1.y);
        xx[k][6] = f2pk(v1.z, v1.z);
        xx[k][7] = f2pk(v1.w, v1.w);
    }

    float best[QPT];
    int   bi[QPT];
    #pragma unroll
    for (int k = 0; k < QPT; k++) { best[k] = -3.402823466e38f; bi[k] = 0; }

    __syncthreads();

    #pragma unroll 2
    for (int j = 0; j < PAIRS_PER_SPLIT; j++) {
        ulonglong2 a01 = s01[j];
        ulonglong2 a23 = s23[j];
        ulonglong2 a45 = s45[j];
        ulonglong2 a67 = s67[j];
        unsigned long long nr = snrm[j];

        unsigned long long acc[QPT];
        #pragma unroll
        for (int k = 0; k < QPT; k++) acc[k] = nr;
        #pragma unroll
        for (int k = 0; k < QPT; k++) acc[k] = ffma2(xx[k][0], a01.x, acc[k]);
        #pragma unroll
        for (int k = 0; k < QPT; k++) acc[k] = ffma2(xx[k][1], a01.y, acc[k]);
        #pragma unroll
        for (int k = 0; k < QPT; k++) acc[k] = ffma2(xx[k][2], a23.x, acc[k]);
        #pragma unroll
        for (int k = 0; k < QPT; k++) acc[k] = ffma2(xx[k][3], a23.y, acc[k]);
        #pragma unroll
        for (int k = 0; k < QPT; k++) acc[k] = ffma2(xx[k][4], a45.x, acc[k]);
        #pragma unroll
        for (int k = 0; k < QPT; k++) acc[k] = ffma2(xx[k][5], a45.y, acc[k]);
        #pragma unroll
        for (int k = 0; k < QPT; k++) acc[k] = ffma2(xx[k][6], a67.x, acc[k]);
        #pragma unroll
        for (int k = 0; k < QPT; k++) acc[k] = ffma2(xx[k][7], a67.y, acc[k]);

        const int ia = (pair_base + j) * 2;
        #pragma unroll
        for (int k = 0; k < QPT; k++) {
            float sc0, sc1;
            f2upk(acc[k], sc0, sc1);
            // Pair-max first, then single predicated update.
            // Ties: sc1==sc0 -> lower index; m==best -> keep earlier index.
            float m  = fmaxf(sc0, sc1);
            int   ii = ia + (sc1 > sc0 ? 1 : 0);
            bool  up = m > best[k];
            best[k] = up ? m  : best[k];
            bi[k]   = up ? ii : bi[k];
        }
    }

    // Deterministic global combine: max on (mono(score), ~idx) packed u64.
    // Higher score wins; equal score -> larger (0xFFFFFFFF - idx) = smaller idx.
    #pragma unroll
    for (int k = 0; k < QPT; k++) {
        unsigned long long pk =
            (((unsigned long long)fmono(best[k])) << 32) |
            (unsigned long long)(0xFFFFFFFFu - (unsigned int)bi[k]);
        atomicMax(&g_best[q0 + k], pk);
    }

    // Split-k semaphore: last CTA to finish this query group does the blend.
    __threadfence();                       // release: my atomicMax visible gpu-wide
    __syncthreads();
    if (tid == 0) s_old = atomicAdd(&g_done[blockIdx.x], 1);
    __syncthreads();

    if (s_old == S_SPLIT - 1) {
        __threadfence();                   // acquire: see all splits' atomicMax
        if (tid == 0) g_done[blockIdx.x] = 0;   // re-arm counter for next replay

        const int b  = q0 >> 11;           // all 4 queries share the same batch
        const int tt = __ldg(&t[b]);
        const float sa = __ldg(&sqrt_ac[tt]);
        const float sb = __ldg(&sqrt_om_ac[tt]);

        float4* out4 = reinterpret_cast<float4*>(out);
        #pragma unroll
        for (int k = 0; k < QPT; k++) {
            const int q = q0 + k;
            unsigned long long pk = __ldcg(&g_best[q]);   // L2 read (atomics live at L2)
            const int widx = (int)(0xFFFFFFFFu - (unsigned int)pk);
            __stcg(&g_best[q], 0ull);      // re-arm winner slot for next replay

            float4 xv0 = x4[2 * q];
            float4 xv1 = x4[2 * q + 1];
            float4 m0  = a4[2 * widx];
            float4 m1  = a4[2 * widx + 1];

            float4 o0, o1;
            o0.x = sa * xv0.x + sb * m0.x;
            o0.y = sa * xv0.y + sb * m0.y;
            o0.z = sa * xv0.z + sb * m0.z;
            o0.w = sa * xv0.w + sb * m0.w;
            o1.x = sa * xv1.x + sb * m1.x;
            o1.y = sa * xv1.y + sb * m1.y;
            o1.z = sa * xv1.z + sb * m1.z;
            o1.w = sa * xv1.w + sb * m1.w;

            out4[2 * q]     = o0;
            out4[2 * q + 1] = o1;
        }
    }
}

extern "C" void kernel_launch(void* const* d_in, const int* in_sizes, int n_in,
                              void* d_out, int out_size) {
    const float* x_start   = (const float*)d_in[0];   // [16,2048,4,2]
    const float* anchors   = (const float*)d_in[1];   // [8192,4,2]
    const float* sqrt_ac   = (const float*)d_in[2];   // [1000]
    const float* sqrt_omac = (const float*)d_in[3];   // [1000]
    const int*   t         = (const int*)d_in[4];     // [16]
    float*       out       = (float*)d_out;           // [16,2048,4,2]

    (void)in_sizes; (void)n_in; (void)out_size;

    dim3 grid(NQGROUP, S_SPLIT);   // 64 x 16 = 1024 CTAs
    nn_fused_kernel<<<grid, BLOCK>>>(x_start, anchors, sqrt_ac,
                                     sqrt_omac, t, out);
}